// round 15
// baseline (speedup 1.0000x reference)
#include <cuda_runtime.h>
#include <cuda_bf16.h>
#include <cuda_fp16.h>
#include <math.h>
#include <cstdint>

#define BSZ  4
#define SEQ  2048
#define DIMM 768
#define NH   12
#define DH   64
#define NTOK (BSZ*SEQ)   // 8192
#define KE   64          // attention: plain fp16 Q x K

// ---------------- scratch (device globals) ----------------------------------
__device__ __align__(256) __half g_a0 [(size_t)NTOK*DIMM];
__device__ __align__(256) __half g_a1 [(size_t)NTOK*DIMM];
__device__ __align__(256) __half g_a2 [(size_t)NTOK*DIMM];
__device__ __align__(256) __half g_w0 [(size_t)DIMM*DIMM];
__device__ __align__(256) __half g_w1 [(size_t)DIMM*DIMM];
__device__ __align__(256) __half g_w2 [(size_t)DIMM*DIMM];
__device__ __align__(256) __half g_w3 [(size_t)DIMM*DIMM];
__device__ __align__(256) __half g_qe [(size_t)BSZ*NH*SEQ*KE];
__device__ __align__(256) __half g_ke [(size_t)BSZ*NH*SEQ*KE];
__device__ __align__(256) __half g_vt [(size_t)BSZ*NH*DH*SEQ];
__device__ __align__(256) __half g_ce [(size_t)NTOK*DIMM];

// ---------------- helpers ---------------------------------------------------
__device__ __forceinline__ uint32_t smem_u32(const void* p) {
    uint32_t a;
    asm("{ .reg .u64 t; cvta.to.shared.u64 t, %1; cvt.u32.u64 %0, t; }" : "=r"(a) : "l"(p));
    return a;
}
__device__ __forceinline__ void ldsm_x4(uint32_t* r, uint32_t addr) {
    asm volatile("ldmatrix.sync.aligned.m8n8.x4.shared.b16 {%0,%1,%2,%3}, [%4];"
                 : "=r"(r[0]), "=r"(r[1]), "=r"(r[2]), "=r"(r[3]) : "r"(addr));
}
__device__ __forceinline__ void ldsm_x2(uint32_t* r, uint32_t addr) {
    asm volatile("ldmatrix.sync.aligned.m8n8.x2.shared.b16 {%0,%1}, [%2];"
                 : "=r"(r[0]), "=r"(r[1]) : "r"(addr));
}
__device__ __forceinline__ void mma_f16(float* d, const uint32_t* a, const uint32_t* b) {
    asm volatile(
        "mma.sync.aligned.m16n8k16.row.col.f32.f16.f16.f32 "
        "{%0,%1,%2,%3}, {%4,%5,%6,%7}, {%8,%9}, {%0,%1,%2,%3};"
        : "+f"(d[0]), "+f"(d[1]), "+f"(d[2]), "+f"(d[3])
        : "r"(a[0]), "r"(a[1]), "r"(a[2]), "r"(a[3]), "r"(b[0]), "r"(b[1]));
}
__device__ __forceinline__ void cpa16(uint32_t dst, const void* src) {
    asm volatile("cp.async.cg.shared.global [%0], [%1], 16;" :: "r"(dst), "l"(src));
}
#define CPA_COMMIT() asm volatile("cp.async.commit_group;" ::: "memory")
#define CPA_WAIT1()  asm volatile("cp.async.wait_group 1;" ::: "memory")
#define CPA_WAIT0()  asm volatile("cp.async.wait_group 0;" ::: "memory")

__device__ __forceinline__ uint32_t packh(float a, float b) {
    __half2 t(__float2half_rn(a), __float2half_rn(b));
    return *reinterpret_cast<uint32_t*>(&t);
}
__device__ __forceinline__ uint32_t ex2_f16x2(uint32_t t) {
    uint32_t r;
    asm("ex2.approx.f16x2 %0, %1;" : "=r"(r) : "r"(t));
    return r;
}

// ---------------------------------------------------------------------------
// Fused convert: all 7 tensors fp32 -> fp16, one launch (blockIdx.y = job).
// ---------------------------------------------------------------------------
__global__ void split_all(const float* __restrict__ q, const float* __restrict__ kt,
                          const float* __restrict__ v,
                          const float* __restrict__ qw, const float* __restrict__ kw,
                          const float* __restrict__ vw, const float* __restrict__ ow,
                          __half* __restrict__ a0, __half* __restrict__ a1,
                          __half* __restrict__ a2, __half* __restrict__ w0,
                          __half* __restrict__ w1, __half* __restrict__ w2,
                          __half* __restrict__ w3)
{
    const int job = blockIdx.y;
    const float* X; __half* Y; int rows;
    switch (job) {
        case 0: X = q;  Y = a0; rows = NTOK; break;
        case 1: X = kt; Y = a1; rows = NTOK; break;
        case 2: X = v;  Y = a2; rows = NTOK; break;
        case 3: X = qw; Y = w0; rows = DIMM; break;
        case 4: X = kw; Y = w1; rows = DIMM; break;
        case 5: X = vw; Y = w2; rows = DIMM; break;
        default: X = ow; Y = w3; rows = DIMM; break;
    }
    const int nquads = rows * 192;
    int i = blockIdx.x * blockDim.x + threadIdx.x;
    if (i >= nquads) return;
    float4 vv = *reinterpret_cast<const float4*>(&X[(size_t)i * 4]);
    uint2 hh;
    hh.x = packh(vv.x, vv.y);
    hh.y = packh(vv.z, vv.w);
    *reinterpret_cast<uint2*>(&Y[(size_t)i * 4]) = hh;
}

// ---------------------------------------------------------------------------
// HMMA fp16 GEMM: K=768, BK=64 (12 stages), 3-stage cp.async.
// Epilogue: smem-staged, fully coalesced 16B stores for all jobs.
// job: 0=Q->q_eff fp16, 1=K->k_eff fp16, 2=V->vt fp16 transposed, 3=O->fp32
// ---------------------------------------------------------------------------
#define NST (DIMM/64)    // 12
#define STG 3
#define GPITCH 144
#define STGB (128*GPITCH)
#define GSMEM (STG*2*STGB)   // 110592 B (>= 69632 needed for fp32 staging)
#define EPIT 136             // staging pitch in elements (halves or floats)

__global__ __launch_bounds__(256, 2)
void gemm_hmma(int zbase,
               const __half* __restrict__ A0, const __half* __restrict__ A1,
               const __half* __restrict__ A2, const __half* __restrict__ A3,
               const __half* __restrict__ W0, const __half* __restrict__ W1,
               const __half* __restrict__ W2, const __half* __restrict__ W3,
               const float* __restrict__ bq, const float* __restrict__ bk,
               const float* __restrict__ bv, const float* __restrict__ bo,
               float* __restrict__ outf,
               __half* __restrict__ qe, __half* __restrict__ kee,
               __half* __restrict__ vt)
{
    extern __shared__ unsigned char smg[];

    const int job = zbase + blockIdx.z;
    const __half* A; const __half* B; const float* bias;
    switch (job) {
        case 0: A = A0; B = W0; bias = bq; break;
        case 1: A = A1; B = W1; bias = bk; break;
        case 2: A = A2; B = W2; bias = bv; break;
        default: A = A3; B = W3; bias = bo; break;
    }

    const int tid    = threadIdx.x;
    const int lane   = tid & 31;
    const int wid    = tid >> 5;
    const int warp_m = wid & 1;
    const int warp_n = wid >> 1;
    const int bm = blockIdx.y * 128;
    const int bn = blockIdx.x * 128;

    const int lc  = tid & 7;
    const int lr0 = tid >> 3;
    const uint32_t smu = smem_u32(smg);

    float acc[4][4][4];
#pragma unroll
    for (int i = 0; i < 4; i++)
#pragma unroll
        for (int j = 0; j < 4; j++)
#pragma unroll
            for (int e = 0; e < 4; e++) acc[i][j][e] = 0.f;

    auto issue = [&](int s) {
        const size_t ke_ = (size_t)s * 64 + lc * 8;
        const uint32_t bo_ = (uint32_t)(s % STG) * (2 * STGB);
#pragma unroll
        for (int p = 0; p < 4; p++) {
            int r = lr0 + 32 * p;
            cpa16(smu + bo_ + r * GPITCH + lc * 16,         &A[(size_t)(bm + r) * DIMM + ke_]);
            cpa16(smu + bo_ + STGB + r * GPITCH + lc * 16,  &B[(size_t)(bn + r) * DIMM + ke_]);
        }
        CPA_COMMIT();
    };

    issue(0);
    issue(1);

    const int arow0 = warp_m * 64 + (lane & 15);
    const int acol  = (lane >> 4) * 16;
    const int brow0 = warp_n * 32 + (lane & 7);
    const int bcol  = ((lane >> 3) & 1) * 16;

    for (int s = 0; s < NST; s++) {
        if (s + 2 < NST) CPA_WAIT1(); else CPA_WAIT0();
        __syncthreads();
        if (s + 2 < NST) issue(s + 2);

        const uint32_t bo_ = (uint32_t)(s % STG) * (2 * STGB);
#pragma unroll
        for (int ks = 0; ks < 4; ks++) {
            uint32_t af[4][4], bf[4][2];
#pragma unroll
            for (int mt = 0; mt < 4; mt++)
                ldsm_x4(af[mt], smu + bo_ + (arow0 + mt * 16) * GPITCH + ks * 32 + acol);
#pragma unroll
            for (int nt = 0; nt < 4; nt++)
                ldsm_x2(bf[nt], smu + bo_ + STGB + (brow0 + nt * 8) * GPITCH + ks * 32 + bcol);
#pragma unroll
            for (int mt = 0; mt < 4; mt++)
#pragma unroll
                for (int nt = 0; nt < 4; nt++)
                    mma_f16(acc[mt][nt], af[mt], bf[nt]);
        }
    }

    // ---- epilogue: stage in smem, then coalesced 16B global stores ----
    __syncthreads();   // mainloop smem reads done; safe to reuse as staging

    const int rbase = warp_m * 64 + (lane >> 2);          // local row
    const int cbase = warp_n * 32 + (lane & 3) * 2;       // local col

    if (job == 3) {
        float* st = reinterpret_cast<float*>(smg);
#pragma unroll
        for (int mt = 0; mt < 4; mt++)
#pragma unroll
            for (int nt = 0; nt < 4; nt++) {
                const int col = cbase + nt * 8;
                const float b0 = bias[bn + col], b1 = bias[bn + col + 1];
#pragma unroll
                for (int rh = 0; rh < 2; rh++) {
                    const int row = rbase + mt * 16 + rh * 8;
                    float2 v = {acc[mt][nt][rh * 2 + 0] + b0,
                                acc[mt][nt][rh * 2 + 1] + b1};
                    *reinterpret_cast<float2*>(&st[row * EPIT + col]) = v;
                }
            }
        __syncthreads();
#pragma unroll
        for (int it = 0; it < 16; it++) {
            int idx = it * 256 + tid;
            int r = idx >> 5, ch = idx & 31;
            float4 v = *reinterpret_cast<const float4*>(&st[r * EPIT + ch * 4]);
            *reinterpret_cast<float4*>(&outf[(size_t)(bm + r) * DIMM + bn + ch * 4]) = v;
        }
    } else if (job == 2) {
        // stage TRANSPOSED: st[col][row]
        __half* st = reinterpret_cast<__half*>(smg);
#pragma unroll
        for (int mt = 0; mt < 4; mt++)
#pragma unroll
            for (int nt = 0; nt < 4; nt++) {
                const int col = cbase + nt * 8;
                const float b0 = bias[bn + col], b1 = bias[bn + col + 1];
#pragma unroll
                for (int rh = 0; rh < 2; rh++) {
                    const int row = rbase + mt * 16 + rh * 8;
                    st[(col)     * EPIT + row] = __float2half_rn(acc[mt][nt][rh * 2 + 0] + b0);
                    st[(col + 1) * EPIT + row] = __float2half_rn(acc[mt][nt][rh * 2 + 1] + b1);
                }
            }
        __syncthreads();
        const int b_  = bm >> 11;
        const int pos0 = bm & 2047;
#pragma unroll
        for (int it = 0; it < 8; it++) {
            int idx = it * 256 + tid;
            int dl = idx >> 4, ch = idx & 15;
            uint4 v = *reinterpret_cast<const uint4*>(&st[dl * EPIT + ch * 8]);
            const int col = bn + dl;
            const int h_ = col >> 6, d = col & 63;
            *reinterpret_cast<uint4*>(
                &vt[((size_t)(b_ * NH + h_) * DH + d) * SEQ + pos0 + ch * 8]) = v;
        }
    } else {
        __half* st = reinterpret_cast<__half*>(smg);
        const float scl = (job == 0) ? 0.125f : 1.0f;
#pragma unroll
        for (int mt = 0; mt < 4; mt++)
#pragma unroll
            for (int nt = 0; nt < 4; nt++) {
                const int col = cbase + nt * 8;
                const float b0 = bias[bn + col], b1 = bias[bn + col + 1];
#pragma unroll
                for (int rh = 0; rh < 2; rh++) {
                    const int row = rbase + mt * 16 + rh * 8;
                    float x0 = (acc[mt][nt][rh * 2 + 0] + b0) * scl;
                    float x1 = (acc[mt][nt][rh * 2 + 1] + b1) * scl;
                    *reinterpret_cast<uint32_t*>(&st[row * EPIT + col]) = packh(x0, x1);
                }
            }
        __syncthreads();
        __half* dst = (job == 0) ? qe : kee;
#pragma unroll
        for (int it = 0; it < 8; it++) {
            int idx = it * 256 + tid;
            int r = idx >> 4, ch = idx & 15;
            uint4 v = *reinterpret_cast<const uint4*>(&st[r * EPIT + ch * 8]);
            const int grow = bm + r;
            const int b_ = grow >> 11, pos = grow & 2047;
            const int col = bn + ch * 8;
            const int h_ = col >> 6, d = col & 63;
            *reinterpret_cast<uint4*>(
                &dst[((size_t)(b_ * NH + h_) * SEQ + pos) * KE + d]) = v;
        }
    }
}

// ---------------------------------------------------------------------------
// HMMA flash attention (fp16), unchanged from round 14.
// ---------------------------------------------------------------------------
#define BR 128
#define BK 64
#define QP 144
#define VP 144
#define QS_OFF 0
#define KS_OFF 18432
#define KBUF   9216
#define VH_OFF 36864
#define VBUF   9216
#define MS_OFF 55296
#define ATT_SMEM 55808

__global__ __launch_bounds__(256, 2)
void attn_hmma(const __half* __restrict__ qe, const __half* __restrict__ ke,
               const __half* __restrict__ vt,
               const int* __restrict__ mask, __half* __restrict__ ctx)
{
    extern __shared__ unsigned char sm[];
    const uint32_t smb = smem_u32(sm);
    const int tid  = threadIdx.x;
    const int lane = tid & 31;
    const int wid  = tid >> 5;
    const int q0   = blockIdx.x * BR;
    const int bh   = blockIdx.y;
    const int b    = bh / NH;
    const int h    = bh - b * NH;

    const __half* qg = qe + ((size_t)bh * SEQ + q0) * KE;
    for (int idx = tid; idx < BR * 8; idx += 256) {
        int row = idx >> 3, ch = idx & 7;
        cpa16(smb + QS_OFF + row * QP + ch * 16,
              reinterpret_cast<const char*>(qg + (size_t)row * KE) + ch * 16);
    }

    auto load_tile = [&](int kt, int buf) {
        const int k0 = kt * BK;
        const __half* kg = ke + ((size_t)bh * SEQ + k0) * KE;
        for (int idx = tid; idx < 64 * 8; idx += 256) {
            int r = idx >> 3, ch = idx & 7;
            cpa16(smb + KS_OFF + buf * KBUF + r * QP + ch * 16,
                  reinterpret_cast<const char*>(kg + (size_t)r * KE) + ch * 16);
        }
        const size_t vg = (size_t)bh * DH * SEQ + k0;
        for (int idx = tid; idx < 64 * 8; idx += 256) {
            int d = idx >> 3, ch = idx & 7;
            cpa16(smb + VH_OFF + buf * VBUF + d * VP + ch * 16,
                  reinterpret_cast<const char*>(vt + vg + (size_t)d * SEQ) + ch * 16);
        }
        if (tid < 16)
            cpa16(smb + MS_OFF + buf * 256 + tid * 16,
                  reinterpret_cast<const char*>(mask + (size_t)b * SEQ + k0) + tid * 16);
    };

    load_tile(0, 0);
    CPA_COMMIT();

    float oacc[9][4];
    float m_[2];
#pragma unroll
    for (int j = 0; j < 9; j++)
#pragma unroll
        for (int e = 0; e < 4; e++) oacc[j][e] = 0.f;
    m_[0] = -1e30f; m_[1] = -1e30f;

    const int l8  = lane & 7;
    const int ms1 = (lane >> 3) & 1;
    const int ms2 = (lane >> 4) & 1;
    const uint32_t qrowadr  = smb + QS_OFF + (wid * 16 + l8 + ms1 * 8) * QP + ms2 * 16;
    const uint32_t krowadr0 = smb + KS_OFF + (l8 + ms1 * 8) * QP + ms2 * 16;
    const int l16 = lane & 15;
    const uint32_t vrowadr0 = smb + VH_OFF + (l16 & 7) * VP + ((l16 >> 3) * 16);
    const int qc = (lane & 3) * 2;
    const int* Msm = reinterpret_cast<const int*>(sm + MS_OFF);

    const uint32_t onesb = ((lane >> 2) == 0) ? 0x3C003C00u : 0u;
    const uint32_t onesB[2] = {onesb, onesb};
    const float L2E = 1.44269504f;

    for (int kt = 0; kt < SEQ / BK; kt++) {
        const int buf = kt & 1;
        CPA_WAIT0();
        __syncthreads();
        if (kt + 1 < SEQ / BK) {
            load_tile(kt + 1, buf ^ 1);
            CPA_COMMIT();
        }

        float sacc[8][4];
#pragma unroll
        for (int j = 0; j < 8; j++)
#pragma unroll
            for (int e = 0; e < 4; e++) sacc[j][e] = 0.f;

#pragma unroll
        for (int ks = 0; ks < KE / 16; ks++) {
            uint32_t af[4], bf[8][2];
            ldsm_x4(af, qrowadr + ks * 32);
#pragma unroll
            for (int j = 0; j < 4; j++) {
                uint32_t t4[4];
                ldsm_x4(t4, krowadr0 + buf * KBUF + j * (16 * QP) + ks * 32);
                bf[2 * j][0]     = t4[0]; bf[2 * j][1]     = t4[2];
                bf[2 * j + 1][0] = t4[1]; bf[2 * j + 1][1] = t4[3];
            }
#pragma unroll
            for (int n = 0; n < 8; n++)
                mma_f16(sacc[n], af, bf[n]);
        }

        const int mbase = buf * 64 + qc;
        float mb[8][2];
#pragma unroll
        for (int j = 0; j < 8; j++) {
            int2 mm = *reinterpret_cast<const int2*>(&Msm[mbase + j * 8]);
            mb[j][0] = mm.x ? 0.f : -1e30f;
            mb[j][1] = mm.y ? 0.f : -1e30f;
        }

        uint32_t p2[8][2];
#pragma unroll
        for (int rh = 0; rh < 2; rh++) {
            float mx = -1e30f;
#pragma unroll
            for (int j = 0; j < 8; j++) {
#pragma unroll
                for (int c = 0; c < 2; c++) {
                    float v = sacc[j][rh * 2 + c] + mb[j][c];
                    sacc[j][rh * 2 + c] = v;
                    mx = fmaxf(mx, v);
                }
            }
            mx = fmaxf(mx, __shfl_xor_sync(0xffffffffu, mx, 1));
            mx = fmaxf(mx, __shfl_xor_sync(0xffffffffu, mx, 2));
            const float mn = fmaxf(m_[rh], mx);
            const float al = __expf(m_[rh] - mn);
            m_[rh] = mn;
            const float mnl = mn * L2E;
#pragma unroll
            for (int j = 0; j < 8; j++) {
                float t0 = fmaf(sacc[j][rh * 2 + 0], L2E, -mnl);
                float t1 = fmaf(sacc[j][rh * 2 + 1], L2E, -mnl);
                p2[j][rh] = ex2_f16x2(packh(t0, t1));
            }
#pragma unroll
            for (int j = 0; j < 9; j++) {
                oacc[j][rh * 2 + 0] *= al;
                oacc[j][rh * 2 + 1] *= al;
            }
        }

#pragma unroll
        for (int t = 0; t < 4; t++) {
            uint32_t A16[4] = {p2[2 * t][0], p2[2 * t][1],
                               p2[2 * t + 1][0], p2[2 * t + 1][1]};
#pragma unroll
            for (int n = 0; n < 8; n++) {
                uint32_t vf[2];
                ldsm_x2(vf, vrowadr0 + buf * VBUF + n * (8 * VP) + t * 32);
                mma_f16(oacc[n], A16, vf);
            }
            mma_f16(oacc[8], A16, onesB);
        }
    }

#pragma unroll
    for (int rh = 0; rh < 2; rh++) {
        const float lv = __shfl_sync(0xffffffffu, oacc[8][rh * 2], lane & 28);
        const float inv = 1.f / lv;
        const int row = wid * 16 + rh * 8 + (lane >> 2);
        const size_t tb = (size_t)(b * SEQ + q0 + row) * DIMM + h * 64 + qc;
#pragma unroll
        for (int j = 0; j < 8; j++) {
            float x0 = oacc[j][rh * 2 + 0] * inv;
            float x1 = oacc[j][rh * 2 + 1] * inv;
            *reinterpret_cast<uint32_t*>(ctx + tb + j * 8) = packh(x0, x1);
        }
    }
}

// ---------------------------------------------------------------------------
extern "C" void kernel_launch(void* const* d_in, const int* in_sizes, int n_in,
                              void* d_out, int out_size)
{
    const float* query = (const float*)d_in[0];
    const float* key_t = (const float*)d_in[1];
    const float* value = (const float*)d_in[2];
    const int*   mask  = (const int*)  d_in[3];
    const float* q_w   = (const float*)d_in[4];
    const float* q_b   = (const float*)d_in[5];
    const float* k_w   = (const float*)d_in[6];
    const float* k_b   = (const float*)d_in[7];
    const float* v_w   = (const float*)d_in[8];
    const float* v_b   = (const float*)d_in[9];
    const float* o_w   = (const float*)d_in[10];
    const float* o_b   = (const float*)d_in[11];
    float* out = (float*)d_out;

    __half *a0, *a1, *a2, *w0, *w1, *w2, *w3, *gqe, *gke, *gvt, *gce;
    cudaGetSymbolAddress((void**)&a0, g_a0);
    cudaGetSymbolAddress((void**)&a1, g_a1);
    cudaGetSymbolAddress((void**)&a2, g_a2);
    cudaGetSymbolAddress((void**)&w0, g_w0);
    cudaGetSymbolAddress((void**)&w1, g_w1);
    cudaGetSymbolAddress((void**)&w2, g_w2);
    cudaGetSymbolAddress((void**)&w3, g_w3);
    cudaGetSymbolAddress((void**)&gqe, g_qe);
    cudaGetSymbolAddress((void**)&gke, g_ke);
    cudaGetSymbolAddress((void**)&gvt, g_vt);
    cudaGetSymbolAddress((void**)&gce, g_ce);

    cudaFuncSetAttribute(attn_hmma,
                         cudaFuncAttributeMaxDynamicSharedMemorySize, ATT_SMEM);
    cudaFuncSetAttribute(gemm_hmma,
                         cudaFuncAttributeMaxDynamicSharedMemorySize, GSMEM);

    split_all<<<dim3((NTOK * 192 + 255) / 256, 7), 256>>>(
        query, key_t, value, q_w, k_w, v_w, o_w, a0, a1, a2, w0, w1, w2, w3);

    // Q,K,V projections: single-term fp16, K=768
    gemm_hmma<<<dim3(DIMM / 128, NTOK / 128, 3), 256, GSMEM>>>(
        0, a0, a1, a2, gce, w0, w1, w2, w3, q_b, k_b, v_b, o_b,
        nullptr, gqe, gke, gvt);

    attn_hmma<<<dim3(SEQ / BR, BSZ * NH), 256, ATT_SMEM>>>(gqe, gke, gvt, mask, gce);

    // O projection: single-term fp16, K=768
    gemm_hmma<<<dim3(DIMM / 128, NTOK / 128, 1), 256, GSMEM>>>(
        3, a0, a1, a2, gce, w0, w1, w2, w3, q_b, k_b, v_b, o_b,
        out, gqe, gke, gvt);
}

// round 16
// speedup vs baseline: 1.5342x; 1.5342x over previous
#include <cuda_runtime.h>
#include <cuda_bf16.h>
#include <cuda_fp16.h>
#include <math.h>
#include <cstdint>

#define BSZ  4
#define SEQ  2048
#define DIMM 768
#define NH   12
#define DH   64
#define NTOK (BSZ*SEQ)   // 8192
#define KE   64          // attention: plain fp16 Q x K

// ---------------- scratch (device globals) ----------------------------------
__device__ __align__(256) __half g_a0 [(size_t)NTOK*DIMM];
__device__ __align__(256) __half g_a1 [(size_t)NTOK*DIMM];
__device__ __align__(256) __half g_a2 [(size_t)NTOK*DIMM];
__device__ __align__(256) __half g_w0 [(size_t)DIMM*DIMM];
__device__ __align__(256) __half g_w1 [(size_t)DIMM*DIMM];
__device__ __align__(256) __half g_w2 [(size_t)DIMM*DIMM];
__device__ __align__(256) __half g_w3 [(size_t)DIMM*DIMM];
__device__ __align__(256) __half g_qe [(size_t)BSZ*NH*SEQ*KE];
__device__ __align__(256) __half g_ke [(size_t)BSZ*NH*SEQ*KE];
__device__ __align__(256) __half g_vt [(size_t)BSZ*NH*DH*SEQ];
__device__ __align__(256) __half g_ce [(size_t)NTOK*DIMM];

// ---------------- helpers ---------------------------------------------------
__device__ __forceinline__ uint32_t smem_u32(const void* p) {
    uint32_t a;
    asm("{ .reg .u64 t; cvta.to.shared.u64 t, %1; cvt.u32.u64 %0, t; }" : "=r"(a) : "l"(p));
    return a;
}
__device__ __forceinline__ void ldsm_x4(uint32_t* r, uint32_t addr) {
    asm volatile("ldmatrix.sync.aligned.m8n8.x4.shared.b16 {%0,%1,%2,%3}, [%4];"
                 : "=r"(r[0]), "=r"(r[1]), "=r"(r[2]), "=r"(r[3]) : "r"(addr));
}
__device__ __forceinline__ void ldsm_x2(uint32_t* r, uint32_t addr) {
    asm volatile("ldmatrix.sync.aligned.m8n8.x2.shared.b16 {%0,%1}, [%2];"
                 : "=r"(r[0]), "=r"(r[1]) : "r"(addr));
}
__device__ __forceinline__ void mma_f16(float* d, const uint32_t* a, const uint32_t* b) {
    asm volatile(
        "mma.sync.aligned.m16n8k16.row.col.f32.f16.f16.f32 "
        "{%0,%1,%2,%3}, {%4,%5,%6,%7}, {%8,%9}, {%0,%1,%2,%3};"
        : "+f"(d[0]), "+f"(d[1]), "+f"(d[2]), "+f"(d[3])
        : "r"(a[0]), "r"(a[1]), "r"(a[2]), "r"(a[3]), "r"(b[0]), "r"(b[1]));
}
__device__ __forceinline__ void cpa16(uint32_t dst, const void* src) {
    asm volatile("cp.async.cg.shared.global [%0], [%1], 16;" :: "r"(dst), "l"(src));
}
#define CPA_COMMIT() asm volatile("cp.async.commit_group;" ::: "memory")
#define CPA_WAIT1()  asm volatile("cp.async.wait_group 1;" ::: "memory")
#define CPA_WAIT0()  asm volatile("cp.async.wait_group 0;" ::: "memory")

__device__ __forceinline__ uint32_t packh(float a, float b) {
    __half2 t(__float2half_rn(a), __float2half_rn(b));
    return *reinterpret_cast<uint32_t*>(&t);
}
__device__ __forceinline__ uint32_t ex2_f16x2(uint32_t t) {
    uint32_t r;
    asm("ex2.approx.f16x2 %0, %1;" : "=r"(r) : "r"(t));
    return r;
}

// ---------------------------------------------------------------------------
// Fused convert: all 7 tensors fp32 -> fp16, one launch (blockIdx.y = job).
// ---------------------------------------------------------------------------
__global__ void split_all(const float* __restrict__ q, const float* __restrict__ kt,
                          const float* __restrict__ v,
                          const float* __restrict__ qw, const float* __restrict__ kw,
                          const float* __restrict__ vw, const float* __restrict__ ow,
                          __half* __restrict__ a0, __half* __restrict__ a1,
                          __half* __restrict__ a2, __half* __restrict__ w0,
                          __half* __restrict__ w1, __half* __restrict__ w2,
                          __half* __restrict__ w3)
{
    const int job = blockIdx.y;
    const float* X; __half* Y; int rows;
    switch (job) {
        case 0: X = q;  Y = a0; rows = NTOK; break;
        case 1: X = kt; Y = a1; rows = NTOK; break;
        case 2: X = v;  Y = a2; rows = NTOK; break;
        case 3: X = qw; Y = w0; rows = DIMM; break;
        case 4: X = kw; Y = w1; rows = DIMM; break;
        case 5: X = vw; Y = w2; rows = DIMM; break;
        default: X = ow; Y = w3; rows = DIMM; break;
    }
    const int nquads = rows * 192;
    int i = blockIdx.x * blockDim.x + threadIdx.x;
    if (i >= nquads) return;
    float4 vv = *reinterpret_cast<const float4*>(&X[(size_t)i * 4]);
    uint2 hh;
    hh.x = packh(vv.x, vv.y);
    hh.y = packh(vv.z, vv.w);
    *reinterpret_cast<uint2*>(&Y[(size_t)i * 4]) = hh;
}

// ---------------------------------------------------------------------------
// HMMA fp16 GEMM (round-14 version, direct-scatter epilogue):
// K=768, BK=64 (12 stages), 3-stage cp.async, one barrier/stage.
// job: 0=Q->q_eff fp16, 1=K->k_eff fp16, 2=V->vt fp16 transposed, 3=O->fp32
// ---------------------------------------------------------------------------
#define NST (DIMM/64)    // 12
#define STG 3
#define GPITCH 144
#define STGB (128*GPITCH)
#define GSMEM (STG*2*STGB)

__global__ __launch_bounds__(256, 2)
void gemm_hmma(int zbase,
               const __half* __restrict__ A0, const __half* __restrict__ A1,
               const __half* __restrict__ A2, const __half* __restrict__ A3,
               const __half* __restrict__ W0, const __half* __restrict__ W1,
               const __half* __restrict__ W2, const __half* __restrict__ W3,
               const float* __restrict__ bq, const float* __restrict__ bk,
               const float* __restrict__ bv, const float* __restrict__ bo,
               float* __restrict__ outf,
               __half* __restrict__ qe, __half* __restrict__ kee,
               __half* __restrict__ vt)
{
    extern __shared__ unsigned char smg[];

    const int job = zbase + blockIdx.z;
    const __half* A; const __half* B; const float* bias;
    switch (job) {
        case 0: A = A0; B = W0; bias = bq; break;
        case 1: A = A1; B = W1; bias = bk; break;
        case 2: A = A2; B = W2; bias = bv; break;
        default: A = A3; B = W3; bias = bo; break;
    }

    const int tid    = threadIdx.x;
    const int lane   = tid & 31;
    const int wid    = tid >> 5;
    const int warp_m = wid & 1;
    const int warp_n = wid >> 1;
    const int bm = blockIdx.y * 128;
    const int bn = blockIdx.x * 128;

    const int lc  = tid & 7;
    const int lr0 = tid >> 3;
    const uint32_t smu = smem_u32(smg);

    float acc[4][4][4];
#pragma unroll
    for (int i = 0; i < 4; i++)
#pragma unroll
        for (int j = 0; j < 4; j++)
#pragma unroll
            for (int e = 0; e < 4; e++) acc[i][j][e] = 0.f;

    auto issue = [&](int s) {
        const size_t ke_ = (size_t)s * 64 + lc * 8;
        const uint32_t bo_ = (uint32_t)(s % STG) * (2 * STGB);
#pragma unroll
        for (int p = 0; p < 4; p++) {
            int r = lr0 + 32 * p;
            cpa16(smu + bo_ + r * GPITCH + lc * 16,         &A[(size_t)(bm + r) * DIMM + ke_]);
            cpa16(smu + bo_ + STGB + r * GPITCH + lc * 16,  &B[(size_t)(bn + r) * DIMM + ke_]);
        }
        CPA_COMMIT();
    };

    issue(0);
    issue(1);

    const int arow0 = warp_m * 64 + (lane & 15);
    const int acol  = (lane >> 4) * 16;
    const int brow0 = warp_n * 32 + (lane & 7);
    const int bcol  = ((lane >> 3) & 1) * 16;

    for (int s = 0; s < NST; s++) {
        if (s + 2 < NST) CPA_WAIT1(); else CPA_WAIT0();
        __syncthreads();
        if (s + 2 < NST) issue(s + 2);

        const uint32_t bo_ = (uint32_t)(s % STG) * (2 * STGB);
#pragma unroll
        for (int ks = 0; ks < 4; ks++) {
            uint32_t af[4][4], bf[4][2];
#pragma unroll
            for (int mt = 0; mt < 4; mt++)
                ldsm_x4(af[mt], smu + bo_ + (arow0 + mt * 16) * GPITCH + ks * 32 + acol);
#pragma unroll
            for (int nt = 0; nt < 4; nt++)
                ldsm_x2(bf[nt], smu + bo_ + STGB + (brow0 + nt * 8) * GPITCH + ks * 32 + bcol);
#pragma unroll
            for (int mt = 0; mt < 4; mt++)
#pragma unroll
                for (int nt = 0; nt < 4; nt++)
                    mma_f16(acc[mt][nt], af[mt], bf[nt]);
        }
    }

    // ---- epilogue (round-14 direct scatter) ----
    const int rbase = bm + warp_m * 64 + (lane >> 2);
    const int cbase = bn + warp_n * 32 + (lane & 3) * 2;
#pragma unroll
    for (int mt = 0; mt < 4; mt++) {
#pragma unroll
        for (int nt = 0; nt < 4; nt++) {
            const int col = cbase + nt * 8;
            const float b0 = bias[col], b1 = bias[col + 1];
            const int r0 = rbase + mt * 16;
#pragma unroll
            for (int rh = 0; rh < 2; rh++) {
                const int row = r0 + rh * 8;
                float x0 = acc[mt][nt][rh * 2 + 0] + b0;
                float x1 = acc[mt][nt][rh * 2 + 1] + b1;
                if (job == 3) {
                    float2 v = {x0, x1};
                    *reinterpret_cast<float2*>(&outf[(size_t)row * DIMM + col]) = v;
                } else {
                    const int b_  = row >> 11, pos = row & 2047;
                    const int h_  = col >> 6,  d   = col & 63;
                    if (job == 0) { x0 *= 0.125f; x1 *= 0.125f; }
                    if (job == 2) {
                        size_t base = ((size_t)(b_ * NH + h_) * DH + d) * SEQ + pos;
                        vt[base]       = __float2half_rn(x0);
                        vt[base + SEQ] = __float2half_rn(x1);
                    } else {
                        __half* dst = (job == 0) ? qe : kee;
                        size_t base = ((size_t)(b_ * NH + h_) * SEQ + pos) * KE + d;
                        *reinterpret_cast<uint32_t*>(dst + base) = packh(x0, x1);
                    }
                }
            }
        }
    }
}

// ---------------------------------------------------------------------------
// HMMA flash attention (fp16). BR=128, 2 CTAs/SM. Q fragments hoisted out of
// the key loop (Q smem never overwritten). ex2.f16x2 softmax; ones-column sum.
// ---------------------------------------------------------------------------
#define BR 128
#define BK 64
#define QP 144
#define VP 144
#define QS_OFF 0
#define KS_OFF 18432
#define KBUF   9216
#define VH_OFF 36864
#define VBUF   9216
#define MS_OFF 55296
#define ATT_SMEM 55808

__global__ __launch_bounds__(256, 2)
void attn_hmma(const __half* __restrict__ qe, const __half* __restrict__ ke,
               const __half* __restrict__ vt,
               const int* __restrict__ mask, __half* __restrict__ ctx)
{
    extern __shared__ unsigned char sm[];
    const uint32_t smb = smem_u32(sm);
    const int tid  = threadIdx.x;
    const int lane = tid & 31;
    const int wid  = tid >> 5;
    const int q0   = blockIdx.x * BR;
    const int bh   = blockIdx.y;
    const int b    = bh / NH;
    const int h    = bh - b * NH;

    const __half* qg = qe + ((size_t)bh * SEQ + q0) * KE;
    for (int idx = tid; idx < BR * 8; idx += 256) {
        int row = idx >> 3, ch = idx & 7;
        cpa16(smb + QS_OFF + row * QP + ch * 16,
              reinterpret_cast<const char*>(qg + (size_t)row * KE) + ch * 16);
    }

    auto load_tile = [&](int kt, int buf) {
        const int k0 = kt * BK;
        const __half* kg = ke + ((size_t)bh * SEQ + k0) * KE;
        for (int idx = tid; idx < 64 * 8; idx += 256) {
            int r = idx >> 3, ch = idx & 7;
            cpa16(smb + KS_OFF + buf * KBUF + r * QP + ch * 16,
                  reinterpret_cast<const char*>(kg + (size_t)r * KE) + ch * 16);
        }
        const size_t vg = (size_t)bh * DH * SEQ + k0;
        for (int idx = tid; idx < 64 * 8; idx += 256) {
            int d = idx >> 3, ch = idx & 7;
            cpa16(smb + VH_OFF + buf * VBUF + d * VP + ch * 16,
                  reinterpret_cast<const char*>(vt + vg + (size_t)d * SEQ) + ch * 16);
        }
        if (tid < 16)
            cpa16(smb + MS_OFF + buf * 256 + tid * 16,
                  reinterpret_cast<const char*>(mask + (size_t)b * SEQ + k0) + tid * 16);
    };

    load_tile(0, 0);
    CPA_COMMIT();

    float oacc[9][4];
    float m_[2];
#pragma unroll
    for (int j = 0; j < 9; j++)
#pragma unroll
        for (int e = 0; e < 4; e++) oacc[j][e] = 0.f;
    m_[0] = -1e30f; m_[1] = -1e30f;

    const int l8  = lane & 7;
    const int ms1 = (lane >> 3) & 1;
    const int ms2 = (lane >> 4) & 1;
    const uint32_t qrowadr  = smb + QS_OFF + (wid * 16 + l8 + ms1 * 8) * QP + ms2 * 16;
    const uint32_t krowadr0 = smb + KS_OFF + (l8 + ms1 * 8) * QP + ms2 * 16;
    const int l16 = lane & 15;
    const uint32_t vrowadr0 = smb + VH_OFF + (l16 & 7) * VP + ((l16 >> 3) * 16);
    const int qc = (lane & 3) * 2;
    const int* Msm = reinterpret_cast<const int*>(sm + MS_OFF);

    const uint32_t onesb = ((lane >> 2) == 0) ? 0x3C003C00u : 0u;
    const uint32_t onesB[2] = {onesb, onesb};
    const float L2E = 1.44269504f;

    // ---- first tile wait + hoist Q fragments into registers (loop-invariant)
    CPA_WAIT0();
    __syncthreads();
    uint32_t qf[4][4];
#pragma unroll
    for (int ks = 0; ks < KE / 16; ks++)
        ldsm_x4(qf[ks], qrowadr + ks * 32);

    for (int kt = 0; kt < SEQ / BK; kt++) {
        const int buf = kt & 1;
        if (kt > 0) {
            CPA_WAIT0();
            __syncthreads();
        }
        if (kt + 1 < SEQ / BK) {
            load_tile(kt + 1, buf ^ 1);
            CPA_COMMIT();
        }

        // ---- S = Q @ K^T (plain fp16, K=64; Q frags in registers) ----
        float sacc[8][4];
#pragma unroll
        for (int j = 0; j < 8; j++)
#pragma unroll
            for (int e = 0; e < 4; e++) sacc[j][e] = 0.f;

#pragma unroll
        for (int ks = 0; ks < KE / 16; ks++) {
            uint32_t bf[8][2];
#pragma unroll
            for (int j = 0; j < 4; j++) {
                uint32_t t4[4];
                ldsm_x4(t4, krowadr0 + buf * KBUF + j * (16 * QP) + ks * 32);
                bf[2 * j][0]     = t4[0]; bf[2 * j][1]     = t4[2];
                bf[2 * j + 1][0] = t4[1]; bf[2 * j + 1][1] = t4[3];
            }
#pragma unroll
            for (int n = 0; n < 8; n++)
                mma_f16(sacc[n], qf[ks], bf[n]);
        }

        // ---- mask bias (hoisted) ----
        const int mbase = buf * 64 + qc;
        float mb[8][2];
#pragma unroll
        for (int j = 0; j < 8; j++) {
            int2 mm = *reinterpret_cast<const int2*>(&Msm[mbase + j * 8]);
            mb[j][0] = mm.x ? 0.f : -1e30f;
            mb[j][1] = mm.y ? 0.f : -1e30f;
        }

        // ---- online softmax: P = 2^((s-mn)*log2e) via ex2.f16x2 ----
        uint32_t p2[8][2];
#pragma unroll
        for (int rh = 0; rh < 2; rh++) {
            float mx = -1e30f;
#pragma unroll
            for (int j = 0; j < 8; j++) {
#pragma unroll
                for (int c = 0; c < 2; c++) {
                    float v = sacc[j][rh * 2 + c] + mb[j][c];
                    sacc[j][rh * 2 + c] = v;
                    mx = fmaxf(mx, v);
                }
            }
            mx = fmaxf(mx, __shfl_xor_sync(0xffffffffu, mx, 1));
            mx = fmaxf(mx, __shfl_xor_sync(0xffffffffu, mx, 2));
            const float mn = fmaxf(m_[rh], mx);
            const float al = __expf(m_[rh] - mn);
            m_[rh] = mn;
            const float mnl = mn * L2E;
#pragma unroll
            for (int j = 0; j < 8; j++) {
                float t0 = fmaf(sacc[j][rh * 2 + 0], L2E, -mnl);
                float t1 = fmaf(sacc[j][rh * 2 + 1], L2E, -mnl);
                p2[j][rh] = ex2_f16x2(packh(t0, t1));
            }
#pragma unroll
            for (int j = 0; j < 9; j++) {
                oacc[j][rh * 2 + 0] *= al;
                oacc[j][rh * 2 + 1] *= al;
            }
        }

        // ---- O += P @ V (single fp16 pass) + row-sum via ones column ----
#pragma unroll
        for (int t = 0; t < 4; t++) {
            uint32_t A16[4] = {p2[2 * t][0], p2[2 * t][1],
                               p2[2 * t + 1][0], p2[2 * t + 1][1]};
#pragma unroll
            for (int n = 0; n < 8; n++) {
                uint32_t vf[2];
                ldsm_x2(vf, vrowadr0 + buf * VBUF + n * (8 * VP) + t * 32);
                mma_f16(oacc[n], A16, vf);
            }
            mma_f16(oacc[8], A16, onesB);
        }
    }

    // ---- finalize ----
#pragma unroll
    for (int rh = 0; rh < 2; rh++) {
        const float lv = __shfl_sync(0xffffffffu, oacc[8][rh * 2], lane & 28);
        const float inv = 1.f / lv;
        const int row = wid * 16 + rh * 8 + (lane >> 2);
        const size_t tb = (size_t)(b * SEQ + q0 + row) * DIMM + h * 64 + qc;
#pragma unroll
        for (int j = 0; j < 8; j++) {
            float x0 = oacc[j][rh * 2 + 0] * inv;
            float x1 = oacc[j][rh * 2 + 1] * inv;
            *reinterpret_cast<uint32_t*>(ctx + tb + j * 8) = packh(x0, x1);
        }
    }
}

// ---------------------------------------------------------------------------
extern "C" void kernel_launch(void* const* d_in, const int* in_sizes, int n_in,
                              void* d_out, int out_size)
{
    const float* query = (const float*)d_in[0];
    const float* key_t = (const float*)d_in[1];
    const float* value = (const float*)d_in[2];
    const int*   mask  = (const int*)  d_in[3];
    const float* q_w   = (const float*)d_in[4];
    const float* q_b   = (const float*)d_in[5];
    const float* k_w   = (const float*)d_in[6];
    const float* k_b   = (const float*)d_in[7];
    const float* v_w   = (const float*)d_in[8];
    const float* v_b   = (const float*)d_in[9];
    const float* o_w   = (const float*)d_in[10];
    const float* o_b   = (const float*)d_in[11];
    float* out = (float*)d_out;

    __half *a0, *a1, *a2, *w0, *w1, *w2, *w3, *gqe, *gke, *gvt, *gce;
    cudaGetSymbolAddress((void**)&a0, g_a0);
    cudaGetSymbolAddress((void**)&a1, g_a1);
    cudaGetSymbolAddress((void**)&a2, g_a2);
    cudaGetSymbolAddress((void**)&w0, g_w0);
    cudaGetSymbolAddress((void**)&w1, g_w1);
    cudaGetSymbolAddress((void**)&w2, g_w2);
    cudaGetSymbolAddress((void**)&w3, g_w3);
    cudaGetSymbolAddress((void**)&gqe, g_qe);
    cudaGetSymbolAddress((void**)&gke, g_ke);
    cudaGetSymbolAddress((void**)&gvt, g_vt);
    cudaGetSymbolAddress((void**)&gce, g_ce);

    cudaFuncSetAttribute(attn_hmma,
                         cudaFuncAttributeMaxDynamicSharedMemorySize, ATT_SMEM);
    cudaFuncSetAttribute(gemm_hmma,
                         cudaFuncAttributeMaxDynamicSharedMemorySize, GSMEM);

    split_all<<<dim3((NTOK * 192 + 255) / 256, 7), 256>>>(
        query, key_t, value, q_w, k_w, v_w, o_w, a0, a1, a2, w0, w1, w2, w3);

    // Q,K,V projections: single-term fp16, K=768
    gemm_hmma<<<dim3(DIMM / 128, NTOK / 128, 3), 256, GSMEM>>>(
        0, a0, a1, a2, gce, w0, w1, w2, w3, q_b, k_b, v_b, o_b,
        nullptr, gqe, gke, gvt);

    attn_hmma<<<dim3(SEQ / BR, BSZ * NH), 256, ATT_SMEM>>>(gqe, gke, gvt, mask, gce);

    // O projection: single-term fp16, K=768
    gemm_hmma<<<dim3(DIMM / 128, NTOK / 128, 1), 256, GSMEM>>>(
        3, a0, a1, a2, gce, w0, w1, w2, w3, q_b, k_b, v_b, o_b,
        out, gqe, gke, gvt);
}